// round 6
// baseline (speedup 1.0000x reference)
#include <cuda_runtime.h>
#include <math.h>

#define Tdim 2048
#define Ddim 256
#define CACT 64
#define CTIME 32
#define NROWS (8 * 2048)
#define LABEL_ID_ 3

#define SW4N (96 * 33)     // float4 slots: weights [c][33]
#define HS4N (128 * 33)    // float4 slots: h tile  [r][33]
#define OBSTR 98

typedef unsigned long long ull;

__device__ float g_scr[(long)NROWS * 96];
__device__ int   g_done[8];

union U4 { float4 f; ull u[2]; };

__device__ __forceinline__ float softplusf(float x) { return log1pf(expf(x)); }
__device__ __forceinline__ ull fma2(ull a, ull b, ull c) {
    ull d; asm("fma.rn.f32x2 %0,%1,%2,%3;" : "=l"(d) : "l"(a), "l"(b), "l"(c)); return d;
}

__global__ void reset_kernel() {
    if (threadIdx.x < 8) g_done[threadIdx.x] = 0;
}

__global__ void __launch_bounds__(256, 1) fat_kernel(
    const int* __restrict__ tokens, const float* __restrict__ h,
    const float* __restrict__ E,
    const float* __restrict__ Wn, const float* __restrict__ bn,
    const float* __restrict__ Wt, const float* __restrict__ bt,
    const float* __restrict__ tsa, const float* __restrict__ tst,
    const float* __restrict__ psa, const float* __restrict__ pst,
    const float* __restrict__ ppa, const float* __restrict__ ppt,
    const float* __restrict__ pta, const float* __restrict__ ptt,
    float* __restrict__ out)
{
    extern __shared__ float sm[];
    int tid = threadIdx.x, lane = tid & 31, wid = tid >> 5;
    int bx = blockIdx.x;

    if (bx >= 24) {
        // ====================== GEMM role ======================
        float4* sW4 = (float4*)sm;            // [c][33] per K-stage
        float4* hs4 = sW4 + SW4N;             // [r][33] per K-stage
        float*  ob  = (float*)hs4;            // output staging (reuse)
        __shared__ int s_lab[128];
        __shared__ int s_nlab;

        int cg = wid;
        long rowbase = (long)(bx - 24) * 128;
        int b = (int)(rowbase >> 11);
        float s_ta = softplusf(*tsa), s_tt = softplusf(*tst);

        if (tid == 0) s_nlab = 0;

        float bsv[12];
#pragma unroll
        for (int j = 0; j < 12; ++j) {
            int c = cg * 12 + j;
            bsv[j] = (c < CACT) ? bn[c] : bt[c - CACT];
        }

        ull acc[4][12];
#pragma unroll
        for (int r = 0; r < 4; ++r)
#pragma unroll
            for (int j = 0; j < 12; ++j) acc[r][j] = 0ull;

        const float4* gh = (const float4*)h;

        for (int stage = 0; stage < 2; ++stage) {
            __syncthreads();
            // fold weights: sW4[c][d4] = W[c] + s*E[class(c)]
#pragma unroll
            for (int k = 0; k < 12; ++k) {
                int i = tid + 256 * k;
                int c = i >> 5, d4 = i & 31;
                const float4* w4 = (const float4*)((c < CACT) ? (Wn + c * Ddim)
                                                              : (Wt + (c - CACT) * Ddim));
                int erow = (c < CACT) ? (4 + c) : (68 + (c - CACT));
                float sc = (c < CACT) ? s_ta : s_tt;
                float4 w = w4[stage * 32 + d4];
                float4 e = ((const float4*)(E + (long)erow * Ddim))[stage * 32 + d4];
                sW4[c * 33 + d4] = make_float4(w.x + sc * e.x, w.y + sc * e.y,
                                               w.z + sc * e.z, w.w + sc * e.w);
            }
            // stage h half
#pragma unroll
            for (int k = 0; k < 16; ++k) {
                int i = tid + 256 * k;
                int r = i >> 5, d4 = i & 31;
                hs4[r * 33 + d4] = gh[(rowbase + r) * 64 + stage * 32 + d4];
            }
            __syncthreads();

            const float4* wb = sW4 + cg * 12 * 33;
#pragma unroll 2
            for (int chunk = 0; chunk < 32; ++chunk) {
                U4 hv[4];
#pragma unroll
                for (int r = 0; r < 4; ++r) hv[r].f = hs4[(lane + 32 * r) * 33 + chunk];
#pragma unroll
                for (int g = 0; g < 2; ++g) {
                    U4 wv[6];
#pragma unroll
                    for (int j = 0; j < 6; ++j) wv[j].f = wb[(g * 6 + j) * 33 + chunk];
#pragma unroll
                    for (int r = 0; r < 4; ++r)
#pragma unroll
                        for (int j = 0; j < 6; ++j)
                            acc[r][g * 6 + j] = fma2(wv[j].u[0], hv[r].u[0], acc[r][g * 6 + j]);
#pragma unroll
                    for (int r = 0; r < 4; ++r)
#pragma unroll
                        for (int j = 0; j < 6; ++j)
                            acc[r][g * 6 + j] = fma2(wv[j].u[1], hv[r].u[1], acc[r][g * 6 + j]);
                }
            }
        }

        // epilogue: horizontal add + bias -> smem stage
        __syncthreads();
#pragma unroll
        for (int r = 0; r < 4; ++r) {
            int row = lane + 32 * r;
#pragma unroll
            for (int j = 0; j < 12; ++j) {
                union { ull u; float2 f; } v; v.u = acc[r][j];
                ob[row * OBSTR + cg * 12 + j] = v.f.x + v.f.y + bsv[j];
            }
        }
        // find label rows in this tile
        if (tid < 128) {
            int tok = tokens[rowbase + tid];
            if (tok == LABEL_ID_) {
                int idx = atomicAdd(&s_nlab, 1);
                s_lab[idx] = tid;
            }
        }
        // wait for proto blocks of this batch, then merge proto sims
        if (tid == 0) {
            while (*(volatile int*)&g_done[b] < 3) __nanosleep(64);
        }
        __syncthreads();
        int nlab = s_nlab;
        for (int i = 0; i < nlab; ++i) {
            int r = s_lab[i];
            if (tid < 96)
                ob[r * OBSTR + tid] += __ldcg(&g_scr[(rowbase + r) * 96 + tid]);
        }
        __syncthreads();

        // coalesced stores
        float* outT = out + (long)NROWS * CACT;
#pragma unroll
        for (int k = 0; k < 16; ++k) {              // act: 4096 float2
            int i = tid + 256 * k;
            int r = i >> 5, c2 = i & 31;
            float2 v = *(float2*)(ob + r * OBSTR + 2 * c2);
            *(float2*)(out + (rowbase + r) * CACT + 2 * c2) = v;
        }
#pragma unroll
        for (int k = 0; k < 8; ++k) {               // time: 2048 float2
            int i = tid + 256 * k;
            int r = i >> 4, c2 = i & 15;
            float2 v = *(float2*)(ob + r * OBSTR + CACT + 2 * c2);
            *(float2*)(outT + (rowbase + r) * CTIME + 2 * c2) = v;
        }
    } else {
        // ====================== proto role ======================
        int b = bx / 3, part = bx % 3;
        int clo = (part == 0) ? 4 : (part == 1) ? 36 : 68;
        int klo = (part == 2) ? 68 : 4;
        int khi = (part == 2) ? 100 : 68;
        int cbase = part * 32;

        float* q    = sm;                    // 32 x 256
        float* hn   = q + 32 * Ddim;         // 256
        float* red  = hn + Ddim;             // 8
        float* n2   = red + 8;               // 32
        int*   ev_t = (int*)(n2 + 32);       // 2048
        int*   ev_n = ev_t + Tdim;           // 2048
        int*   toks = ev_n + Tdim;           // 2048
        __shared__ int s_nev;
        __shared__ float s_dq;

        for (int i = tid; i < Tdim; i += 256) toks[i] = tokens[(long)b * Tdim + i];
        __syncthreads();

        if (wid == 0) {
            int cnt = 0;
            for (int ch = 0; ch < Tdim / 32; ++ch) {
                int t = ch * 32 + lane;
                bool isl = (toks[t] == LABEL_ID_);
                unsigned m = __ballot_sync(0xffffffffu, isl);
                if (isl) {
                    int idx = cnt + __popc(m & ((1u << lane) - 1u));
                    ev_t[idx] = t;
                    ev_n[idx] = toks[(t + 1) & (Tdim - 1)];
                }
                cnt += __popc(m);
            }
            if (lane == 0) s_nev = cnt;
        }

        float alpha = softplusf(part == 2 ? *ppt : *ppa);
        float scale = softplusf(part == 2 ? *pst : *psa) * softplusf(part == 2 ? *ptt : *pta);

        // q[c] = alpha * l2norm(E[clo + c])   (warp per class)
        for (int c = wid; c < 32; c += 8) {
            const float* e = E + (long)(clo + c) * Ddim;
            float v[8]; float ss = 0.f;
#pragma unroll
            for (int k = 0; k < 8; ++k) { v[k] = e[lane + 32 * k]; ss += v[k] * v[k]; }
#pragma unroll
            for (int o = 16; o > 0; o >>= 1) ss += __shfl_xor_sync(0xffffffffu, ss, o);
            float inv = alpha / fmaxf(sqrtf(ss), 1e-12f);
#pragma unroll
            for (int k = 0; k < 8; ++k) q[c * Ddim + lane + 32 * k] = v[k] * inv;
        }
        if (tid < 32) n2[tid] = alpha * alpha;
        __syncthreads();

        int nev = s_nev;
        const float* hb = h + (long)b * Tdim * Ddim;
        int cnt = 0;
        float hv = (nev > 0) ? hb[(long)ev_t[0] * Ddim + tid] : 0.f;

        for (int e = 0; e < nev; ++e) {
            int t = ev_t[e], ntok = ev_n[e];

            float ss = hv * hv;
#pragma unroll
            for (int o = 16; o > 0; o >>= 1) ss += __shfl_xor_sync(0xffffffffu, ss, o);
            if (lane == 0) red[wid] = ss;
            __syncthreads();                                   // (1)
            float tot = red[0] + red[1] + red[2] + red[3]
                      + red[4] + red[5] + red[6] + red[7];
            float inv = 1.0f / fmaxf(sqrtf(tot), 1e-12f);
            float hn2 = tot * inv * inv;
            hn[tid] = hv * inv;
            __syncthreads();                                   // (2)
            if (e + 1 < nev) hv = hb[(long)ev_t[e + 1] * Ddim + tid];

            bool supk = (ntok >= klo) && (ntok < khi);
            bool supm = (ntok >= clo) && (ntok < clo + 32);
            int cls = ntok - clo;

            int c = tid >> 3, seg = tid & 7;
            const float* qc = q + c * Ddim + seg * 32;
            const float* hc = hn + seg * 32;
            float s1 = 0.f;
#pragma unroll
            for (int i = 0; i < 32; ++i) {
                int dd = (i + lane) & 31;
                s1 += qc[dd] * hc[dd];
            }
#pragma unroll
            for (int o = 1; o < 8; o <<= 1) s1 += __shfl_xor_sync(0xffffffffu, s1, o);
            if (seg == 0) {
                if (supm && c == cls) s_dq = s1;
                float val = (cnt > 0) ? scale * s1 * rsqrtf(n2[c]) : 0.f;
                g_scr[((long)b * Tdim + t) * 96 + cbase + c] = val;
            }
            __syncthreads();                                   // (3)

            if (supm) {
                q[cls * Ddim + tid] += hn[tid];
                if (tid == 0) n2[cls] += 2.f * s_dq + hn2;
            }
            if (supk) cnt++;
        }

        // publish: all sims for this (b, part) are in g_scr
        __syncthreads();
        if (tid == 0) {
            __threadfence();
            atomicAdd(&g_done[b], 1);
        }
    }
}

extern "C" void kernel_launch(void* const* d_in, const int* in_sizes, int n_in,
                              void* d_out, int out_size)
{
    size_t smem = (size_t)(SW4N + HS4N) * 16;
    cudaFuncSetAttribute(fat_kernel, cudaFuncAttributeMaxDynamicSharedMemorySize, (int)smem);

    reset_kernel<<<1, 32>>>();

    fat_kernel<<<152, 256, smem>>>(
        (const int*)d_in[0], (const float*)d_in[1], (const float*)d_in[2],
        (const float*)d_in[3], (const float*)d_in[4],
        (const float*)d_in[5], (const float*)d_in[6],
        (const float*)d_in[7], (const float*)d_in[8],
        (const float*)d_in[9], (const float*)d_in[10],
        (const float*)d_in[11], (const float*)d_in[12],
        (const float*)d_in[13], (const float*)d_in[14],
        (float*)d_out);
}